// round 1
// baseline (speedup 1.0000x reference)
#include <cuda_runtime.h>

#define VP   32    // points per voxel
#define CIN  4
#define CH   16
#define COUT 16
#define LN_EPS 1e-5f

// ---------------------------------------------------------------------------
// Kernel 1: zero-fill the dense output grid (512 MB). float4 stores, ~peak BW.
// ---------------------------------------------------------------------------
__global__ void dvpn_zero_kernel(float4* __restrict__ out, long long n4) {
    long long i = (long long)blockIdx.x * blockDim.x + threadIdx.x;
    if (i < n4) out[i] = make_float4(0.f, 0.f, 0.f, 0.f);
}

// ---------------------------------------------------------------------------
// Kernel 2: one warp per voxel.
//   lane p (< num_points): feat[4] @ W1 + b1 -> LN(16) -> relu -> h[16]
//   warp butterfly-reduce h over lanes (masked)
//   lanes 0..15: x[o] = sum_k h[k]*W2[k][o] + n*b2[o]; LN over the 16 lanes;
//   scatter 16 floats (one 64B segment) to the dense grid.
// ---------------------------------------------------------------------------
__global__ void dvpn_voxel_kernel(
    const float* __restrict__ features,     // [V, 32, 4]
    const int*   __restrict__ num_points,   // [V]
    const int*   __restrict__ coords,       // [V, 4] (b, ix, iy, iz)
    const float* __restrict__ W1,           // [4, 16]
    const float* __restrict__ b1,           // [16]
    const float* __restrict__ g1,           // [16]
    const float* __restrict__ be1,          // [16]
    const float* __restrict__ W2,           // [16, 16]
    const float* __restrict__ b2,           // [16]
    const float* __restrict__ g2,           // [16]
    const float* __restrict__ be2,          // [16]
    const int*   __restrict__ pB,
    const int*   __restrict__ pGH,
    const int*   __restrict__ pGW,
    const int*   __restrict__ pGZ,
    float*       __restrict__ out,          // [B, GH, GW, GZ, 16]
    int V)
{
    __shared__ float sW1[CIN * CH];      // 64
    __shared__ float sW2[CH * COUT];     // 256
    __shared__ float sb1[CH], sg1[CH], sbe1[CH];
    __shared__ float sb2[COUT], sg2[COUT], sbe2[COUT];

    const int tid = threadIdx.x;
    for (int i = tid; i < CIN * CH; i += blockDim.x) sW1[i] = W1[i];
    for (int i = tid; i < CH * COUT; i += blockDim.x) sW2[i] = W2[i];
    if (tid < CH) {
        sb1[tid]  = b1[tid];
        sg1[tid]  = g1[tid];
        sbe1[tid] = be1[tid];
        sb2[tid]  = b2[tid];
        sg2[tid]  = g2[tid];
        sbe2[tid] = be2[tid];
    }
    __syncthreads();

    const int warp = (int)((blockIdx.x * blockDim.x + tid) >> 5);
    const int lane = tid & 31;
    if (warp >= V) return;

    // num_points: one load, broadcast
    int n = 0;
    if (lane == 0) n = num_points[warp];
    n = __shfl_sync(0xffffffffu, n, 0);

    // ---- per-point MLP1 + LN + relu (lane p = point p) ----
    float h[CH];
    #pragma unroll
    for (int j = 0; j < CH; j++) h[j] = 0.f;

    if (lane < n) {
        float4 f = reinterpret_cast<const float4*>(features)[warp * VP + lane];
        float t[CH];
        float mu = 0.f;
        #pragma unroll
        for (int j = 0; j < CH; j++) {
            float tv = sb1[j];
            tv = fmaf(f.x, sW1[0 * CH + j], tv);
            tv = fmaf(f.y, sW1[1 * CH + j], tv);
            tv = fmaf(f.z, sW1[2 * CH + j], tv);
            tv = fmaf(f.w, sW1[3 * CH + j], tv);
            t[j] = tv;
            mu += tv;
        }
        mu *= (1.f / CH);
        float var = 0.f;
        #pragma unroll
        for (int j = 0; j < CH; j++) {
            float d = t[j] - mu;
            var = fmaf(d, d, var);
        }
        var *= (1.f / CH);
        float r = rsqrtf(var + LN_EPS);
        #pragma unroll
        for (int j = 0; j < CH; j++) {
            float y = fmaf((t[j] - mu) * r, sg1[j], sbe1[j]);
            h[j] = fmaxf(y, 0.f);
        }
    }

    // ---- warp reduce: Sigma over masked points for each channel ----
    #pragma unroll
    for (int j = 0; j < CH; j++) {
        #pragma unroll
        for (int o = 16; o > 0; o >>= 1)
            h[j] += __shfl_xor_sync(0xffffffffu, h[j], o);
    }
    // every lane now holds the full sum vector h[0..15]

    // ---- MLP2 (per voxel): lane o in [0,16) owns output channel o ----
    float xv = 0.f;
    {
        const int o = lane & 15;          // lanes 16..31 compute garbage, unused
        xv = (float)n * sb2[o];
        #pragma unroll
        for (int k = 0; k < CH; k++)
            xv = fmaf(h[k], sW2[k * COUT + o], xv);
    }

    // ---- LN over the 16 output channels (group-of-16 shfl; lanes 16..31
    //      form their own harmless group) ----
    float mu2 = xv;
    #pragma unroll
    for (int o = 8; o > 0; o >>= 1) mu2 += __shfl_xor_sync(0xffffffffu, mu2, o);
    mu2 *= (1.f / COUT);
    float d2 = xv - mu2;
    float var2 = d2 * d2;
    #pragma unroll
    for (int o = 8; o > 0; o >>= 1) var2 += __shfl_xor_sync(0xffffffffu, var2, o);
    var2 *= (1.f / COUT);

    if (lane < COUT) {
        float y = fmaf(d2 * rsqrtf(var2 + LN_EPS), sg2[lane], sbe2[lane]);

        int4 c = reinterpret_cast<const int4*>(coords)[warp];
        const int B  = *pB;
        const int GH = *pGH;
        const int GW = *pGW;
        const int GZ = *pGZ;
        // mode='drop': bounds check
        if (c.x >= 0 && c.x < B && c.y >= 0 && c.y < GH &&
            c.z >= 0 && c.z < GW && c.w >= 0 && c.w < GZ) {
            long long off =
                ((((long long)c.x * GH + c.y) * GW + c.z) * GZ + c.w) * COUT + lane;
            out[off] = y;
        }
    }
}

// ---------------------------------------------------------------------------
extern "C" void kernel_launch(void* const* d_in, const int* in_sizes, int n_in,
                              void* d_out, int out_size) {
    const float* features   = (const float*)d_in[0];
    const int*   num_points = (const int*)  d_in[1];
    const int*   coords     = (const int*)  d_in[2];
    const float* W1  = (const float*)d_in[3];
    const float* b1  = (const float*)d_in[4];
    const float* g1  = (const float*)d_in[5];
    const float* be1 = (const float*)d_in[6];
    const float* W2  = (const float*)d_in[7];
    const float* b2  = (const float*)d_in[8];
    const float* g2  = (const float*)d_in[9];
    const float* be2 = (const float*)d_in[10];
    const int*   pB  = (const int*)d_in[11];
    const int*   pGH = (const int*)d_in[12];
    const int*   pGW = (const int*)d_in[13];
    const int*   pGZ = (const int*)d_in[14];
    float* out = (float*)d_out;

    const int V = in_sizes[1];  // num_points element count

    // 1) zero the dense grid (out_size is a multiple of 16 floats -> of 4)
    long long n4 = (long long)out_size / 4;
    int zblocks = (int)((n4 + 255) / 256);
    dvpn_zero_kernel<<<zblocks, 256>>>((float4*)out, n4);

    // 2) voxel compute + scatter (8 warps / block of 256)
    int vblocks = (V + 7) / 8;
    dvpn_voxel_kernel<<<vblocks, 256>>>(
        features, num_points, coords,
        W1, b1, g1, be1, W2, b2, g2, be2,
        pB, pGH, pGW, pGZ, out, V);
}

// round 2
// speedup vs baseline: 1.1842x; 1.1842x over previous
#include <cuda_runtime.h>

#define VP   32
#define CIN  4
#define CH   16
#define COUT 16
#define W2S  17            // padded row stride for bank-conflict-free reads
#define LN_EPS 1e-5f

// ---------------------------------------------------------------------------
// Kernel 1: zero-fill the dense output grid (512 MB) at DRAM-write peak.
// ---------------------------------------------------------------------------
__global__ void dvpn_zero_kernel(float4* __restrict__ out, long long n4) {
    long long i = (long long)blockIdx.x * blockDim.x + threadIdx.x;
    if (i < n4) out[i] = make_float4(0.f, 0.f, 0.f, 0.f);
}

// ---------------------------------------------------------------------------
// Kernel 2: 2 voxels per warp, 16 lanes/voxel, 2 points/lane.
// Register-halving butterfly reductions (15 SHFL per 16ch x 16-lane sum).
// ---------------------------------------------------------------------------
__global__ __launch_bounds__(256) void dvpn_voxel_kernel(
    const float* __restrict__ features,     // [V, 32, 4]
    const int*   __restrict__ num_points,   // [V]
    const int*   __restrict__ coords,       // [V, 4]
    const float* __restrict__ W1,           // [4, 16]
    const float* __restrict__ b1,
    const float* __restrict__ g1,
    const float* __restrict__ be1,
    const float* __restrict__ W2,           // [16, 16]
    const float* __restrict__ b2,
    const float* __restrict__ g2,
    const float* __restrict__ be2,
    const int*   __restrict__ pB,
    const int*   __restrict__ pGH,
    const int*   __restrict__ pGW,
    const int*   __restrict__ pGZ,
    float*       __restrict__ out,
    int V)
{
    __shared__ float sW1[CIN * CH];
    __shared__ float sW2[CH * W2S];
    __shared__ float sb1[CH], sg1[CH], sbe1[CH];
    __shared__ float sb2[COUT], sg2[COUT], sbe2[COUT];
    __shared__ int   sdim[4];

    const int tid = threadIdx.x;
    if (tid < CIN * CH) sW1[tid] = W1[tid];
    if (tid < CH * COUT) sW2[(tid >> 4) * W2S + (tid & 15)] = W2[tid];
    if (tid < CH) {
        sb1[tid]  = b1[tid];  sg1[tid]  = g1[tid];  sbe1[tid] = be1[tid];
        sb2[tid]  = b2[tid];  sg2[tid]  = g2[tid];  sbe2[tid] = be2[tid];
    }
    if (tid == 0) { sdim[0] = *pB; sdim[1] = *pGH; sdim[2] = *pGW; sdim[3] = *pGZ; }
    __syncthreads();

    const int gwarp = blockIdx.x * (blockDim.x >> 5) + (tid >> 5);
    const int lane  = tid & 31;
    const int sub   = lane & 15;           // lane within voxel group
    const int v     = gwarp * 2 + (lane >> 4);
    const bool valid = (v < V);
    const int vv = valid ? v : 0;

    const int n = valid ? num_points[vv] : 0;

    // ---- per-point MLP1 + LN + relu, 2 points per lane, accumulate ----
    float hs[CH];
    #pragma unroll
    for (int j = 0; j < CH; j++) hs[j] = 0.f;

    const float4* feat4 = reinterpret_cast<const float4*>(features);
    #pragma unroll
    for (int pp = 0; pp < 2; pp++) {
        const int p = sub + pp * 16;
        if (p < n) {
            float4 f = feat4[(long long)vv * VP + p];
            float t[CH];
            float mu = 0.f;
            #pragma unroll
            for (int j = 0; j < CH; j++) {
                float tv = sb1[j];
                tv = fmaf(f.x, sW1[0 * CH + j], tv);
                tv = fmaf(f.y, sW1[1 * CH + j], tv);
                tv = fmaf(f.z, sW1[2 * CH + j], tv);
                tv = fmaf(f.w, sW1[3 * CH + j], tv);
                t[j] = tv;
                mu += tv;
            }
            mu *= (1.f / CH);
            float var = 0.f;
            #pragma unroll
            for (int j = 0; j < CH; j++) {
                float d = t[j] - mu;
                var = fmaf(d, d, var);
            }
            float r = rsqrtf(fmaf(var, 1.f / CH, LN_EPS));
            #pragma unroll
            for (int j = 0; j < CH; j++) {
                float y = fmaf((t[j] - mu) * r, sg1[j], sbe1[j]);
                hs[j] += fmaxf(y, 0.f);
            }
        }
    }

    // ---- halving butterfly: sum 16 channels over 16 lanes (15 SHFL) ----
    // stage mask=1: 16 -> 8
    #pragma unroll
    for (int i = 0; i < 8; i++) {
        bool hi = (lane & 1);
        float send = hi ? hs[i] : hs[i + 8];
        float keep = hi ? hs[i + 8] : hs[i];
        hs[i] = keep + __shfl_xor_sync(0xffffffffu, send, 1);
    }
    // mask=2: 8 -> 4
    #pragma unroll
    for (int i = 0; i < 4; i++) {
        bool hi = (lane & 2);
        float send = hi ? hs[i] : hs[i + 4];
        float keep = hi ? hs[i + 4] : hs[i];
        hs[i] = keep + __shfl_xor_sync(0xffffffffu, send, 2);
    }
    // mask=4: 4 -> 2
    #pragma unroll
    for (int i = 0; i < 2; i++) {
        bool hi = (lane & 4);
        float send = hi ? hs[i] : hs[i + 2];
        float keep = hi ? hs[i + 2] : hs[i];
        hs[i] = keep + __shfl_xor_sync(0xffffffffu, send, 4);
    }
    // mask=8: 2 -> 1
    {
        bool hi = (lane & 8);
        float send = hi ? hs[0] : hs[1];
        float keep = hi ? hs[1] : hs[0];
        hs[0] = keep + __shfl_xor_sync(0xffffffffu, send, 8);
    }
    // lane holds S at channel c1 = bitrev4(sub)
    const float S  = hs[0];
    const int   c1 = (int)(__brev((unsigned)sub) >> 28);

    // ---- MLP2 distributed: p[o] = S * W2[c1][o] (+ n*b2[o] on lane c1==0) ----
    float pr[COUT];
    const float bias2 = (c1 == 0) ? (float)n : 0.f;
    #pragma unroll
    for (int o = 0; o < COUT; o++)
        pr[o] = fmaf(bias2, sb2[o], S * sW2[c1 * W2S + o]);

    // ---- second halving reduction over the 16 outputs (15 SHFL) ----
    #pragma unroll
    for (int i = 0; i < 8; i++) {
        bool hi = (lane & 1);
        float send = hi ? pr[i] : pr[i + 8];
        float keep = hi ? pr[i + 8] : pr[i];
        pr[i] = keep + __shfl_xor_sync(0xffffffffu, send, 1);
    }
    #pragma unroll
    for (int i = 0; i < 4; i++) {
        bool hi = (lane & 2);
        float send = hi ? pr[i] : pr[i + 4];
        float keep = hi ? pr[i + 4] : pr[i];
        pr[i] = keep + __shfl_xor_sync(0xffffffffu, send, 2);
    }
    #pragma unroll
    for (int i = 0; i < 2; i++) {
        bool hi = (lane & 4);
        float send = hi ? pr[i] : pr[i + 2];
        float keep = hi ? pr[i + 2] : pr[i];
        pr[i] = keep + __shfl_xor_sync(0xffffffffu, send, 4);
    }
    {
        bool hi = (lane & 8);
        float send = hi ? pr[0] : pr[1];
        float keep = hi ? pr[1] : pr[0];
        pr[0] = keep + __shfl_xor_sync(0xffffffffu, send, 8);
    }
    const float x  = pr[0];                 // output channel c2 = bitrev4(sub)
    const int   c2 = c1;

    // ---- LN over the 16 outputs (8 SHFL, half-warp scope) ----
    float mu2 = x;
    #pragma unroll
    for (int m = 1; m <= 8; m <<= 1) mu2 += __shfl_xor_sync(0xffffffffu, mu2, m);
    mu2 *= (1.f / COUT);
    float d2 = x - mu2;
    float var2 = d2 * d2;
    #pragma unroll
    for (int m = 1; m <= 8; m <<= 1) var2 += __shfl_xor_sync(0xffffffffu, var2, m);
    float y = fmaf(d2 * rsqrtf(fmaf(var2, 1.f / COUT, LN_EPS)), sg2[c2], sbe2[c2]);

    // ---- scatter (mode='drop' bounds check) ----
    if (valid) {
        int4 c = reinterpret_cast<const int4*>(coords)[vv];
        const int B  = sdim[0], GH = sdim[1], GW = sdim[2], GZ = sdim[3];
        if (c.x >= 0 && c.x < B && c.y >= 0 && c.y < GH &&
            c.z >= 0 && c.z < GW && c.w >= 0 && c.w < GZ) {
            long long off =
                ((((long long)c.x * GH + c.y) * GW + c.z) * GZ + c.w) * COUT + c2;
            out[off] = y;
        }
    }
}

// ---------------------------------------------------------------------------
extern "C" void kernel_launch(void* const* d_in, const int* in_sizes, int n_in,
                              void* d_out, int out_size) {
    const float* features   = (const float*)d_in[0];
    const int*   num_points = (const int*)  d_in[1];
    const int*   coords     = (const int*)  d_in[2];
    const float* W1  = (const float*)d_in[3];
    const float* b1  = (const float*)d_in[4];
    const float* g1  = (const float*)d_in[5];
    const float* be1 = (const float*)d_in[6];
    const float* W2  = (const float*)d_in[7];
    const float* b2  = (const float*)d_in[8];
    const float* g2  = (const float*)d_in[9];
    const float* be2 = (const float*)d_in[10];
    const int*   pB  = (const int*)d_in[11];
    const int*   pGH = (const int*)d_in[12];
    const int*   pGW = (const int*)d_in[13];
    const int*   pGZ = (const int*)d_in[14];
    float* out = (float*)d_out;

    const int V = in_sizes[1];

    long long n4 = (long long)out_size / 4;
    int zblocks = (int)((n4 + 255) / 256);
    dvpn_zero_kernel<<<zblocks, 256>>>((float4*)out, n4);

    // 2 voxels per warp, 8 warps per block -> 16 voxels per block
    int vblocks = (V + 15) / 16;
    dvpn_voxel_kernel<<<vblocks, 256>>>(
        features, num_points, coords,
        W1, b1, g1, be1, W2, b2, g2, be2,
        pB, pGH, pGW, pGZ, out, V);
}